// round 13
// baseline (speedup 1.0000x reference)
#include <cuda_runtime.h>
#include <math_constants.h>

// Offsets with +1 bias: 0 = "not ready" (matches static zero-init on first
// run), value v>0 means first row of that segment is v-1. Last-finishing
// block re-zeros everything so each graph replay starts clean.
__device__ int g_offs[65537];
__device__ unsigned g_fini = 0;

// ---------------------------------------------------------------------------
// Fused single kernel. Grid = G blocks, 128 threads.
// Blocks 0..NB-1 first scan one 1024-id chunk of the SORTED segment_ids
// (8 ids/thread, int4/longlong2 loads + scalar successor) and publish
// biased boundary values with plain stores (the value is its own ready
// flag). ALL blocks then poll just their two entries (threads 0 and 32,
// independent warps), and run the measured-best pool loop. The last block
// to finish zeroes g_offs[0..G] and g_fini for replay determinism.
// ---------------------------------------------------------------------------
__global__ void __launch_bounds__(128, 12)
seg_pool_fused_kernel(const float* __restrict__ x, const void* __restrict__ seg,
                      float* __restrict__ out, int n, int G, int NB) {
    const int blk  = blockIdx.x;
    const int tid  = threadIdx.x;
    const int lane = tid & 31;
    const int grp  = tid >> 5;

    // ---------------- Phase 1: boundary scan (blocks 0..NB-1) ----------------
    if (blk < NB) {
        const int base = (blk * 128 + tid) * 8;
        if (base < n) {
            // dtype sniff (warp-uniform): int64 word at n/4 covers int32
            // elements n/2, n/2+1. Sorted ids: middle ~G/2 != 0, so int32
            // read as int64 is >= 2^32; genuine int64 stays a small id.
            const long long probe = ((const long long*)seg)[n >> 2];
            const bool is64 = (probe >= 0) && (probe < (1LL << 31));

            int v[9];  // 8 owned ids + successor (sentinel G past the end)
            if (base + 8 <= n) {
                if (is64) {
                    const longlong2* p =
                        (const longlong2*)((const long long*)seg + base);
                    #pragma unroll
                    for (int j = 0; j < 4; j++) {
                        longlong2 a = __ldg(&p[j]);
                        v[2 * j]     = (int)a.x;
                        v[2 * j + 1] = (int)a.y;
                    }
                } else {
                    const int4* p = (const int4*)((const int*)seg + base);
                    int4 a = __ldg(&p[0]);
                    int4 b = __ldg(&p[1]);
                    v[0] = a.x; v[1] = a.y; v[2] = a.z; v[3] = a.w;
                    v[4] = b.x; v[5] = b.y; v[6] = b.z; v[7] = b.w;
                }
                v[8] = (base + 8 < n)
                         ? (is64 ? (int)((const long long*)seg)[base + 8]
                                 : ((const int*)seg)[base + 8])
                         : G;
            } else {
                #pragma unroll
                for (int j = 0; j < 9; j++) {
                    const int idx = base + j;
                    v[j] = (idx < n)
                             ? (is64 ? (int)((const long long*)seg)[idx]
                                     : ((const int*)seg)[idx])
                             : G;
                }
            }

            // publish biased values; a 4B aligned store is atomic, and the
            // nonzero value itself signals readiness.
            volatile int* offs = g_offs;
            if (base == 0) {
                for (int s = 0; s <= v[0]; s++) offs[s] = 1;        // row 0
            }
            #pragma unroll
            for (int j = 0; j < 8; j++) {
                // first row of every segment in (v[j], v[j+1]] is base+j+1
                const int val = base + j + 2;                        // +1 bias
                for (int s = v[j] + 1; s <= v[j + 1]; s++) offs[s] = val;
            }
        }
    }

    // ---------------- Phase 2: poll the two needed entries ----------------
    const int g = blk;
    __shared__ int sb[2];
    if (lane == 0 && grp < 2) {
        volatile int* p = &g_offs[g + grp];
        int v = *p;
        while (v == 0) { __nanosleep(64); v = *p; }
        sb[grp] = v - 1;
    }
    __syncthreads();

    const int start = sb[0];
    const int end   = sb[1];

    float4 s  = make_float4(0.f, 0.f, 0.f, 0.f);
    float4 q  = make_float4(0.f, 0.f, 0.f, 0.f);
    float4 mx = make_float4(-CUDART_INF_F, -CUDART_INF_F, -CUDART_INF_F, -CUDART_INF_F);
    float4 mn = make_float4( CUDART_INF_F,  CUDART_INF_F,  CUDART_INF_F,  CUDART_INF_F);

    const float4* __restrict__ xv = (const float4*)x;  // row stride = 32 float4

    #pragma unroll 4
    for (int r = start + grp; r < end; r += 4) {
        float4 v = __ldcs(&xv[(size_t)r * 32 + lane]);
        s.x += v.x; s.y += v.y; s.z += v.z; s.w += v.w;
        q.x = fmaf(v.x, v.x, q.x); q.y = fmaf(v.y, v.y, q.y);
        q.z = fmaf(v.z, v.z, q.z); q.w = fmaf(v.w, v.w, q.w);
        mx.x = fmaxf(mx.x, v.x); mx.y = fmaxf(mx.y, v.y);
        mx.z = fmaxf(mx.z, v.z); mx.w = fmaxf(mx.w, v.w);
        mn.x = fminf(mn.x, v.x); mn.y = fminf(mn.y, v.y);
        mn.z = fminf(mn.z, v.z); mn.w = fminf(mn.w, v.w);
    }

    // partials: [stat][group][lane] as float4 -> 8 KB
    __shared__ float4 sm4[4][4][32];
    sm4[0][grp][lane] = s;
    sm4[1][grp][lane] = q;
    sm4[2][grp][lane] = mx;
    sm4[3][grp][lane] = mn;
    __syncthreads();

    // thread f in [0,128) combines the 4 group partials for feature f
    const int f = threadIdx.x;
    float sum = 0.f, sq = 0.f;
    float M = -CUDART_INF_F, m = CUDART_INF_F;
    #pragma unroll
    for (int k = 0; k < 4; k++) {
        const float* p0 = (const float*)&sm4[0][k][0];
        const float* p1 = (const float*)&sm4[1][k][0];
        const float* p2 = (const float*)&sm4[2][k][0];
        const float* p3 = (const float*)&sm4[3][k][0];
        sum += p0[f];
        sq  += p1[f];
        M = fmaxf(M, p2[f]);
        m = fminf(m, p3[f]);
    }

    const float cnt  = (float)(end - start);
    const float mean = sum / cnt;
    const float var  = (sq - cnt * mean * mean) / (cnt - 1.0f);
    const float sd   = sqrtf(fmaxf(var, 0.0f));

    float* o = out + (size_t)g * 512;  // [4][128] per segment
    o[f]        = M;
    o[128 + f]  = m;
    o[256 + f]  = mean;
    o[384 + f]  = sd;

    // ---------------- Replay reset: last block zeroes the state ----------------
    __syncthreads();
    __shared__ int s_last;
    if (tid == 0) {
        __threadfence();
        unsigned old = atomicAdd(&g_fini, 1u);
        s_last = (old == gridDim.x - 1) ? 1 : 0;
    }
    __syncthreads();
    if (s_last) {
        for (int i = tid; i <= G; i += 128) g_offs[i] = 0;
        __syncthreads();
        if (tid == 0) {
            __threadfence();
            atomicExch(&g_fini, 0u);
        }
    }
}

extern "C" void kernel_launch(void* const* d_in, const int* in_sizes, int n_in,
                              void* d_out, int out_size) {
    const float* x   = (const float*)d_in[0];
    const void*  seg = d_in[1];
    float* out = (float*)d_out;

    const int D = 128;
    const int n = in_sizes[0] / D;          // number of rows
    const int G = out_size / (4 * D);       // number of segments

    // scan chunk = 128 threads * 8 ids = 1024 ids per block
    const int NB = (n + 1023) / 1024;       // 1024 for n = 1M

    seg_pool_fused_kernel<<<G, 128>>>(x, seg, out, n, G, NB);
}

// round 17
// speedup vs baseline: 1.0194x; 1.0194x over previous
#include <cuda_runtime.h>
#include <math_constants.h>

// Scratch for segment offsets (allocation-free rule: __device__ global).
__device__ int g_offsets[65537];

// ---------------------------------------------------------------------------
// Kernel 1: streaming boundary scan over the SORTED segment_ids array.
// Thread i reads seg[i] and seg[i+1]; at each transition it fills the
// offsets for every id in (seg[i], seg[i+1]]. Edge threads fill the head
// ([0, seg[0]]) and tail ((seg[n-1], G]). One coalesced pass (~2us).
// Handles both int64 (reference dtype) and int32 (JAX default) via sniffing.
// ---------------------------------------------------------------------------
__global__ void seg_boundaries_kernel(const void* __restrict__ seg, int n, int G) {
    const int i = blockIdx.x * blockDim.x + threadIdx.x;
    if (i >= n) return;

    // dtype sniff: int64 word at index n/4 covers int32 elements n/2, n/2+1.
    // Sorted ids: middle element ~G/2 != 0, so int32 data read as int64 is
    // >= 2^32; genuine int64 data stays a small id.
    const long long probe = ((const long long*)seg)[n >> 2];
    const bool is64 = (probe >= 0) && (probe < (1LL << 31));

    int id, next;
    if (is64) {
        const long long* s = (const long long*)seg;
        id   = (int)s[i];
        next = (i + 1 < n) ? (int)s[i + 1] : G;
    } else {
        const int* s = (const int*)seg;
        id   = s[i];
        next = (i + 1 < n) ? s[i + 1] : G;
    }

    if (i == 0) {
        for (int g = 0; g <= id; g++) g_offsets[g] = 0;
    }
    // first row of every segment in (id, next] is i+1
    for (int g = id + 1; g <= next; g++) g_offsets[g] = i + 1;
}

// ---------------------------------------------------------------------------
// Kernel 2 (measured-best configuration): one block per segment. 128 threads
// = 4 row-groups x 32 lanes. Lane l owns features [4l, 4l+4) via float4
// (coalesced LDG.128, streaming hint). Row-group r processes rows start+r,
// start+r+4, ... Cross-group combine in shared memory, then thread f writes
// the 4 stats for feature f.
// ---------------------------------------------------------------------------
__global__ void __launch_bounds__(128, 12)
seg_pool_kernel(const float* __restrict__ x, float* __restrict__ out, int G) {
    const int g = blockIdx.x;
    const int start = g_offsets[g];
    const int end   = g_offsets[g + 1];

    const int lane = threadIdx.x & 31;
    const int grp  = threadIdx.x >> 5;

    float4 s  = make_float4(0.f, 0.f, 0.f, 0.f);
    float4 q  = make_float4(0.f, 0.f, 0.f, 0.f);
    float4 mx = make_float4(-CUDART_INF_F, -CUDART_INF_F, -CUDART_INF_F, -CUDART_INF_F);
    float4 mn = make_float4( CUDART_INF_F,  CUDART_INF_F,  CUDART_INF_F,  CUDART_INF_F);

    const float4* __restrict__ xv = (const float4*)x;  // row stride = 32 float4

    #pragma unroll 4
    for (int r = start + grp; r < end; r += 4) {
        float4 v = __ldcs(&xv[(size_t)r * 32 + lane]);
        s.x += v.x; s.y += v.y; s.z += v.z; s.w += v.w;
        q.x = fmaf(v.x, v.x, q.x); q.y = fmaf(v.y, v.y, q.y);
        q.z = fmaf(v.z, v.z, q.z); q.w = fmaf(v.w, v.w, q.w);
        mx.x = fmaxf(mx.x, v.x); mx.y = fmaxf(mx.y, v.y);
        mx.z = fmaxf(mx.z, v.z); mx.w = fmaxf(mx.w, v.w);
        mn.x = fminf(mn.x, v.x); mn.y = fminf(mn.y, v.y);
        mn.z = fminf(mn.z, v.z); mn.w = fminf(mn.w, v.w);
    }

    // partials: [stat][group][lane] as float4 -> 4*4*32*16B = 8 KB
    __shared__ float4 sm4[4][4][32];
    sm4[0][grp][lane] = s;
    sm4[1][grp][lane] = q;
    sm4[2][grp][lane] = mx;
    sm4[3][grp][lane] = mn;
    __syncthreads();

    // thread f in [0,128) combines the 4 group partials for feature f
    const int f = threadIdx.x;
    float sum = 0.f, sq = 0.f;
    float M = -CUDART_INF_F, m = CUDART_INF_F;
    #pragma unroll
    for (int k = 0; k < 4; k++) {
        const float* p0 = (const float*)&sm4[0][k][0];
        const float* p1 = (const float*)&sm4[1][k][0];
        const float* p2 = (const float*)&sm4[2][k][0];
        const float* p3 = (const float*)&sm4[3][k][0];
        sum += p0[f];
        sq  += p1[f];
        M = fmaxf(M, p2[f]);
        m = fminf(m, p3[f]);
    }

    const float cnt  = (float)(end - start);
    const float mean = sum / cnt;
    const float var  = (sq - cnt * mean * mean) / (cnt - 1.0f);
    const float sd   = sqrtf(fmaxf(var, 0.0f));

    float* o = out + (size_t)g * 512;  // [4][128] per segment
    o[f]        = M;
    o[128 + f]  = m;
    o[256 + f]  = mean;
    o[384 + f]  = sd;
}

extern "C" void kernel_launch(void* const* d_in, const int* in_sizes, int n_in,
                              void* d_out, int out_size) {
    const float* x   = (const float*)d_in[0];
    const void*  seg = d_in[1];
    float* out = (float*)d_out;

    const int D = 128;
    const int n = in_sizes[0] / D;          // number of rows
    const int G = out_size / (4 * D);       // number of segments

    int tb = 256;
    int nb = (n + tb - 1) / tb;
    seg_boundaries_kernel<<<nb, tb>>>(seg, n, G);
    seg_pool_kernel<<<G, 128>>>(x, out, G);
}